// round 1
// baseline (speedup 1.0000x reference)
#include <cuda_runtime.h>

#define T_TOK 4096     // B*S
#define DMODEL 1024
#define NEXP 8
#define FFN 2048
#define TOPK 2

// ---------------- device scratch (static: no runtime allocation) ----------------
__device__ int   g_cnt[NEXP];
__device__ int   g_off[NEXP + 1];
__device__ int   g_fill[NEXP];
__device__ int   g_pair_tok[T_TOK * TOPK];
__device__ float g_pair_gate[T_TOK * TOPK];
__device__ int   g_top_e[T_TOK * TOPK];
__device__ float g_top_w[T_TOK * TOPK];
__device__ float g_h[(size_t)T_TOK * TOPK * FFN];   // 64 MiB intermediate h

// ---------------- packed f32x2 helpers (FFMA2 path: 2x fp32 rate on sm_103a) ----
__device__ __forceinline__ unsigned long long dup2(float x) {
    unsigned long long r;
    asm("mov.b64 %0, {%1, %1};" : "=l"(r) : "f"(x));
    return r;
}
__device__ __forceinline__ void ffma2(unsigned long long& d, unsigned long long a,
                                      unsigned long long b) {
    asm("fma.rn.f32x2 %0, %1, %2, %0;" : "+l"(d) : "l"(a), "l"(b));
}
__device__ __forceinline__ float2 unpk(unsigned long long v) {
    float2 r;
    asm("mov.b64 {%0, %1}, %2;" : "=f"(r.x), "=f"(r.y) : "l"(v));
    return r;
}

// ---------------- init: zero output + counters ----------------
__global__ void init_kernel(float* __restrict__ out, int n) {
    int i = blockIdx.x * blockDim.x + threadIdx.x;
    if (i < n) out[i] = 0.0f;
    if (i < NEXP) { g_cnt[i] = 0; g_fill[i] = 0; }
}

// ---------------- router: logits -> softmax -> top2 -> L1-renorm ----------------
__global__ void router_kernel(const float* __restrict__ x, const float* __restrict__ rw) {
    const int t   = blockIdx.x;
    const int tid = threadIdx.x;   // 256 threads; each owns one float4 chunk of the row
    const float4 xr = reinterpret_cast<const float4*>(x + (size_t)t * DMODEL)[tid];

    float part[NEXP];
#pragma unroll
    for (int e = 0; e < NEXP; ++e) {
        const float4 w = reinterpret_cast<const float4*>(rw + (size_t)e * DMODEL)[tid];
        part[e] = xr.x * w.x + xr.y * w.y + xr.z * w.z + xr.w * w.w;
    }
#pragma unroll
    for (int e = 0; e < NEXP; ++e) {
#pragma unroll
        for (int o = 16; o > 0; o >>= 1)
            part[e] += __shfl_down_sync(0xffffffffu, part[e], o);
    }
    __shared__ float sm[NEXP][8];
    const int warp = tid >> 5, lane = tid & 31;
    if (lane == 0) {
#pragma unroll
        for (int e = 0; e < NEXP; ++e) sm[e][warp] = part[e];
    }
    __syncthreads();
    if (tid == 0) {
        float lg[NEXP];
        float mx = -1e30f;
#pragma unroll
        for (int e = 0; e < NEXP; ++e) {
            float s = 0.f;
#pragma unroll
            for (int w = 0; w < 8; ++w) s += sm[e][w];
            lg[e] = s;
            mx = fmaxf(mx, s);
        }
        float den = 0.f;
#pragma unroll
        for (int e = 0; e < NEXP; ++e) { lg[e] = expf(lg[e] - mx); den += lg[e]; }
#pragma unroll
        for (int e = 0; e < NEXP; ++e) lg[e] /= den;

        // top-2 (ties -> lowest index, matching jax top_k)
        int e0 = 0; float v0 = lg[0];
#pragma unroll
        for (int e = 1; e < NEXP; ++e) if (lg[e] > v0) { v0 = lg[e]; e0 = e; }
        int e1 = -1; float v1 = -1.f;
#pragma unroll
        for (int e = 0; e < NEXP; ++e)
            if (e != e0 && lg[e] > v1) { v1 = lg[e]; e1 = e; }

        const float nrm = v0 + v1;           // both positive -> L1 norm
        const float g0 = v0 / nrm, g1 = v1 / nrm;
        g_top_e[t * 2 + 0] = e0;  g_top_w[t * 2 + 0] = g0;
        g_top_e[t * 2 + 1] = e1;  g_top_w[t * 2 + 1] = g1;
        atomicAdd(&g_cnt[e0], 1);
        atomicAdd(&g_cnt[e1], 1);
    }
}

// ---------------- prefix-sum of counts (8 values, 1 thread) ----------------
__global__ void offsets_kernel() {
    g_off[0] = 0;
    for (int e = 0; e < NEXP; ++e) g_off[e + 1] = g_off[e] + g_cnt[e];
}

// ---------------- build per-expert (token, gate) lists ----------------
__global__ void scatter_kernel() {
    int t = blockIdx.x * blockDim.x + threadIdx.x;
    if (t >= T_TOK) return;
#pragma unroll
    for (int k = 0; k < TOPK; ++k) {
        int e = g_top_e[t * TOPK + k];
        int pos = g_off[e] + atomicAdd(&g_fill[e], 1);
        g_pair_tok[pos]  = t;
        g_pair_gate[pos] = g_top_w[t * TOPK + k];
    }
}

// ---------------- GEMM1: h = silu(x@w1_e^T) * (x@v1_e^T), gathered rows --------
// Tile: 128 (pairs) x 64 (F) x 16 (D-chunk), 256 threads, each thread 8x4 dual acc.
__global__ void __launch_bounds__(256) gemm1_kernel(const float* __restrict__ x,
                                                    const float* __restrict__ w1,
                                                    const float* __restrict__ v1) {
    const int e   = blockIdx.y;
    const int n0  = blockIdx.x * 64;
    const int off = g_off[e];
    const int cnt = g_cnt[e];

    __shared__ __align__(16) float As[128][16];
    __shared__ __align__(16) float W1s[16][66];   // [k][n], transposed store
    __shared__ __align__(16) float V1s[16][66];
    __shared__ int toks[128];

    const int tid = threadIdx.x;
    const int tx = tid & 15, ty = tid >> 4;     // 16 x 16
    const int lr = tid >> 2;                    // 0..63
    const int lk = (tid & 3) * 4;               // 0,4,8,12

    for (int mt = blockIdx.z; mt * 128 < cnt; mt += gridDim.z) {
        if (tid < 128) {
            int r = mt * 128 + tid;
            toks[tid] = (r < cnt) ? g_pair_tok[off + r] : -1;
        }
        unsigned long long acc1[8][2], acc2[8][2];
#pragma unroll
        for (int i = 0; i < 8; ++i) {
            acc1[i][0] = acc1[i][1] = 0ull;
            acc2[i][0] = acc2[i][1] = 0ull;
        }
        __syncthreads();

        for (int k0 = 0; k0 < DMODEL; k0 += 16) {
            // A: gathered x rows (two 64-row groups)
#pragma unroll
            for (int g = 0; g < 2; ++g) {
                int row = lr + g * 64;
                int tok = toks[row];
                float4 v = make_float4(0.f, 0.f, 0.f, 0.f);
                if (tok >= 0)
                    v = *reinterpret_cast<const float4*>(x + (size_t)tok * DMODEL + k0 + lk);
                *reinterpret_cast<float4*>(&As[row][lk]) = v;
            }
            // W: 64 F-rows x 16 D, transposed into [k][n]
            {
                const size_t gbase = ((size_t)e * FFN + n0 + lr) * DMODEL + k0 + lk;
                const float4 a = *reinterpret_cast<const float4*>(w1 + gbase);
                W1s[lk + 0][lr] = a.x; W1s[lk + 1][lr] = a.y;
                W1s[lk + 2][lr] = a.z; W1s[lk + 3][lr] = a.w;
                const float4 b = *reinterpret_cast<const float4*>(v1 + gbase);
                V1s[lk + 0][lr] = b.x; V1s[lk + 1][lr] = b.y;
                V1s[lk + 2][lr] = b.z; V1s[lk + 3][lr] = b.w;
            }
            __syncthreads();
#pragma unroll
            for (int k = 0; k < 16; ++k) {
                const unsigned long long b1a =
                    *reinterpret_cast<const unsigned long long*>(&W1s[k][tx * 4]);
                const unsigned long long b1b =
                    *reinterpret_cast<const unsigned long long*>(&W1s[k][tx * 4 + 2]);
                const unsigned long long b2a =
                    *reinterpret_cast<const unsigned long long*>(&V1s[k][tx * 4]);
                const unsigned long long b2b =
                    *reinterpret_cast<const unsigned long long*>(&V1s[k][tx * 4 + 2]);
#pragma unroll
                for (int i = 0; i < 8; ++i) {
                    const unsigned long long a = dup2(As[ty * 8 + i][k]);
                    ffma2(acc1[i][0], a, b1a);
                    ffma2(acc1[i][1], a, b1b);
                    ffma2(acc2[i][0], a, b2a);
                    ffma2(acc2[i][1], a, b2b);
                }
            }
            __syncthreads();
        }
        // epilogue: SwiGLU, write h
#pragma unroll
        for (int i = 0; i < 8; ++i) {
            int r = mt * 128 + ty * 8 + i;
            if (r < cnt) {
                float2 ga = unpk(acc1[i][0]), gb = unpk(acc1[i][1]);
                float2 la = unpk(acc2[i][0]), lb = unpk(acc2[i][1]);
                float4 hv;
                hv.x = ga.x / (1.f + __expf(-ga.x)) * la.x;
                hv.y = ga.y / (1.f + __expf(-ga.y)) * la.y;
                hv.z = gb.x / (1.f + __expf(-gb.x)) * lb.x;
                hv.w = gb.y / (1.f + __expf(-gb.y)) * lb.y;
                *reinterpret_cast<float4*>(
                    &g_h[(size_t)(off + r) * FFN + n0 + tx * 4]) = hv;
            }
        }
        __syncthreads();
    }
}

// ---------------- GEMM2: y = h @ w2_e, gate-scaled scatter-add into out --------
// Tile: 128 (pairs) x 64 (D) x 16 (F-chunk)
__global__ void __launch_bounds__(256) gemm2_kernel(const float* __restrict__ w2,
                                                    float* __restrict__ out) {
    const int e   = blockIdx.y;
    const int n0  = blockIdx.x * 64;
    const int off = g_off[e];
    const int cnt = g_cnt[e];

    __shared__ __align__(16) float As[128][16];
    __shared__ __align__(16) float Ws[16][68];   // [k][n], direct float4 store

    const int tid = threadIdx.x;
    const int tx = tid & 15, ty = tid >> 4;
    const int lr = tid >> 2;            // 0..63 (A rows)
    const int lk = (tid & 3) * 4;       // A k-offset
    const int wk = tid >> 4;            // 0..15 (W k-rows)
    const int wn = (tid & 15) * 4;      // W n-offset

    for (int mt = blockIdx.z; mt * 128 < cnt; mt += gridDim.z) {
        unsigned long long acc[8][2];
#pragma unroll
        for (int i = 0; i < 8; ++i) { acc[i][0] = 0ull; acc[i][1] = 0ull; }

        for (int k0 = 0; k0 < FFN; k0 += 16) {
#pragma unroll
            for (int g = 0; g < 2; ++g) {
                int r = mt * 128 + lr + g * 64;
                float4 v = make_float4(0.f, 0.f, 0.f, 0.f);
                if (r < cnt)
                    v = *reinterpret_cast<const float4*>(
                        &g_h[(size_t)(off + r) * FFN + k0 + lk]);
                *reinterpret_cast<float4*>(&As[lr + g * 64][lk]) = v;
            }
            {
                const float4 v = *reinterpret_cast<const float4*>(
                    w2 + ((size_t)e * FFN + k0 + wk) * DMODEL + n0 + wn);
                *reinterpret_cast<float4*>(&Ws[wk][wn]) = v;
            }
            __syncthreads();
#pragma unroll
            for (int k = 0; k < 16; ++k) {
                const unsigned long long ba =
                    *reinterpret_cast<const unsigned long long*>(&Ws[k][tx * 4]);
                const unsigned long long bb =
                    *reinterpret_cast<const unsigned long long*>(&Ws[k][tx * 4 + 2]);
#pragma unroll
                for (int i = 0; i < 8; ++i) {
                    const unsigned long long a = dup2(As[ty * 8 + i][k]);
                    ffma2(acc[i][0], a, ba);
                    ffma2(acc[i][1], a, bb);
                }
            }
            __syncthreads();
        }
        // epilogue: gate * y, atomic combine (exactly 2 adds/element -> deterministic)
#pragma unroll
        for (int i = 0; i < 8; ++i) {
            int r = mt * 128 + ty * 8 + i;
            if (r < cnt) {
                const int   tok = g_pair_tok[off + r];
                const float gt  = g_pair_gate[off + r];
                float2 p0 = unpk(acc[i][0]);
                float2 p1 = unpk(acc[i][1]);
                float* dst = out + (size_t)tok * DMODEL + n0 + tx * 4;
                atomicAdd(dst + 0, gt * p0.x);
                atomicAdd(dst + 1, gt * p0.y);
                atomicAdd(dst + 2, gt * p1.x);
                atomicAdd(dst + 3, gt * p1.y);
            }
        }
    }
}

// ---------------- launch ----------------
extern "C" void kernel_launch(void* const* d_in, const int* in_sizes, int n_in,
                              void* d_out, int out_size) {
    const float* x  = (const float*)d_in[0];
    const float* w1 = (const float*)d_in[1];
    const float* v1 = (const float*)d_in[2];
    const float* w2 = (const float*)d_in[3];
    const float* rw = (const float*)d_in[4];
    float* out = (float*)d_out;

    init_kernel<<<(T_TOK * DMODEL + 255) / 256, 256>>>(out, T_TOK * DMODEL);
    router_kernel<<<T_TOK, 256>>>(x, rw);
    offsets_kernel<<<1, 1>>>();
    scatter_kernel<<<(T_TOK + 255) / 256, 256>>>();
    gemm1_kernel<<<dim3(FFN / 64, NEXP, 4), 256>>>(x, w1, v1);
    gemm2_kernel<<<dim3(DMODEL / 64, NEXP, 8), 256>>>(w2, out);
}

// round 4
// speedup vs baseline: 3.0259x; 3.0259x over previous
#include <cuda_runtime.h>
#include <cuda_bf16.h>

#define T_TOK 4096
#define DMODEL 1024
#define NEXP 8
#define FFN 2048
#define TOPK 2
#define NPAIR (T_TOK * TOPK)

// ---------------- device scratch ----------------
__device__ int   g_cnt[NEXP];
__device__ int   g_off[NEXP + 1];
__device__ int   g_fill[NEXP];
__device__ int   g_pair_tok[NPAIR];
__device__ float g_pair_gate[NPAIR];
__device__ int   g_top_e[NPAIR];
__device__ float g_top_w[NPAIR];

__device__ __align__(16) __nv_bfloat16 g_xs_hi[(size_t)T_TOK * DMODEL];
__device__ __align__(16) __nv_bfloat16 g_xs_lo[(size_t)T_TOK * DMODEL];
__device__ __align__(16) __nv_bfloat16 g_w1_hi[(size_t)NEXP * FFN * DMODEL];
__device__ __align__(16) __nv_bfloat16 g_w1_lo[(size_t)NEXP * FFN * DMODEL];
__device__ __align__(16) __nv_bfloat16 g_v1_hi[(size_t)NEXP * FFN * DMODEL];
__device__ __align__(16) __nv_bfloat16 g_v1_lo[(size_t)NEXP * FFN * DMODEL];
__device__ __align__(16) __nv_bfloat16 g_w2t_hi[(size_t)NEXP * DMODEL * FFN];
__device__ __align__(16) __nv_bfloat16 g_w2t_lo[(size_t)NEXP * DMODEL * FFN];
__device__ __align__(16) float g_g[(size_t)NPAIR * FFN];
__device__ __align__(16) float g_l[(size_t)NPAIR * FFN];
__device__ __align__(16) __nv_bfloat16 g_h_hi[(size_t)NPAIR * FFN];
__device__ __align__(16) __nv_bfloat16 g_h_lo[(size_t)NPAIR * FFN];

// ---------------- helpers ----------------
__device__ __forceinline__ unsigned smem_u32(const void* p) {
    unsigned a;
    asm("{ .reg .u64 t; cvta.to.shared.u64 t, %1; cvt.u32.u64 %0, t; }"
        : "=r"(a) : "l"(p));
    return a;
}
// swizzled byte offset in a [rows][32 bf16] tile (64B rows); c must be < 64
__device__ __forceinline__ unsigned swz(int row, int c) {
    return (unsigned)(row * 64 + (c ^ ((row & 6) << 3)));
}
__device__ __forceinline__ void ldm4(unsigned* r, unsigned addr) {
    asm volatile("ldmatrix.sync.aligned.m8n8.x4.shared.b16 {%0,%1,%2,%3}, [%4];"
                 : "=r"(r[0]), "=r"(r[1]), "=r"(r[2]), "=r"(r[3]) : "r"(addr));
}
__device__ __forceinline__ void mma16816(float* c, const unsigned* a, const unsigned* b) {
    asm volatile(
        "mma.sync.aligned.m16n8k16.row.col.f32.bf16.bf16.f32 "
        "{%0,%1,%2,%3}, {%4,%5,%6,%7}, {%8,%9}, {%0,%1,%2,%3};"
        : "+f"(c[0]), "+f"(c[1]), "+f"(c[2]), "+f"(c[3])
        : "r"(a[0]), "r"(a[1]), "r"(a[2]), "r"(a[3]), "r"(b[0]), "r"(b[1]));
}

// ---------------- init ----------------
__global__ void init_kernel(float* __restrict__ out, int n) {
    int i = blockIdx.x * blockDim.x + threadIdx.x;
    if (i < n) out[i] = 0.0f;
    if (i < NEXP) { g_cnt[i] = 0; g_fill[i] = 0; }
}

// ---------------- router ----------------
__global__ void router_kernel(const float* __restrict__ x, const float* __restrict__ rw) {
    const int t   = blockIdx.x;
    const int tid = threadIdx.x;
    const float4 xr = reinterpret_cast<const float4*>(x + (size_t)t * DMODEL)[tid];
    float part[NEXP];
#pragma unroll
    for (int e = 0; e < NEXP; ++e) {
        const float4 w = reinterpret_cast<const float4*>(rw + (size_t)e * DMODEL)[tid];
        part[e] = xr.x * w.x + xr.y * w.y + xr.z * w.z + xr.w * w.w;
    }
#pragma unroll
    for (int e = 0; e < NEXP; ++e)
#pragma unroll
        for (int o = 16; o > 0; o >>= 1)
            part[e] += __shfl_down_sync(0xffffffffu, part[e], o);
    __shared__ float sm[NEXP][8];
    const int warp = tid >> 5, lane = tid & 31;
    if (lane == 0)
#pragma unroll
        for (int e = 0; e < NEXP; ++e) sm[e][warp] = part[e];
    __syncthreads();
    if (tid == 0) {
        float lg[NEXP]; float mx = -1e30f;
#pragma unroll
        for (int e = 0; e < NEXP; ++e) {
            float s = 0.f;
#pragma unroll
            for (int w = 0; w < 8; ++w) s += sm[e][w];
            lg[e] = s; mx = fmaxf(mx, s);
        }
        float den = 0.f;
#pragma unroll
        for (int e = 0; e < NEXP; ++e) { lg[e] = expf(lg[e] - mx); den += lg[e]; }
#pragma unroll
        for (int e = 0; e < NEXP; ++e) lg[e] /= den;
        int e0 = 0; float v0 = lg[0];
#pragma unroll
        for (int e = 1; e < NEXP; ++e) if (lg[e] > v0) { v0 = lg[e]; e0 = e; }
        int e1 = -1; float v1 = -1.f;
#pragma unroll
        for (int e = 0; e < NEXP; ++e)
            if (e != e0 && lg[e] > v1) { v1 = lg[e]; e1 = e; }
        const float nrm = v0 + v1;
        g_top_e[t * 2 + 0] = e0; g_top_w[t * 2 + 0] = v0 / nrm;
        g_top_e[t * 2 + 1] = e1; g_top_w[t * 2 + 1] = v1 / nrm;
        atomicAdd(&g_cnt[e0], 1);
        atomicAdd(&g_cnt[e1], 1);
    }
}

__global__ void offsets_kernel() {
    g_off[0] = 0;
    for (int e = 0; e < NEXP; ++e) g_off[e + 1] = g_off[e] + g_cnt[e];
}

__global__ void scatter_kernel() {
    int t = blockIdx.x * blockDim.x + threadIdx.x;
    if (t >= T_TOK) return;
#pragma unroll
    for (int k = 0; k < TOPK; ++k) {
        int e = g_top_e[t * TOPK + k];
        int pos = g_off[e] + atomicAdd(&g_fill[e], 1);
        g_pair_tok[pos]  = t;
        g_pair_gate[pos] = g_top_w[t * TOPK + k];
    }
}

// ---------------- generic fp32 -> bf16 hi/lo split ----------------
__global__ void split_kernel(const float* __restrict__ s, __nv_bfloat16* __restrict__ hi,
                             __nv_bfloat16* __restrict__ lo, int n4) {
    int i = blockIdx.x * blockDim.x + threadIdx.x;
    if (i >= n4) return;
    float4 v = reinterpret_cast<const float4*>(s)[i];
    __nv_bfloat16 h0 = __float2bfloat16(v.x), h1 = __float2bfloat16(v.y);
    __nv_bfloat16 h2 = __float2bfloat16(v.z), h3 = __float2bfloat16(v.w);
    __nv_bfloat162* ph = reinterpret_cast<__nv_bfloat162*>(hi) + i * 2;
    ph[0] = __nv_bfloat162(h0, h1);
    ph[1] = __nv_bfloat162(h2, h3);
    __nv_bfloat162* pl = reinterpret_cast<__nv_bfloat162*>(lo) + i * 2;
    pl[0] = __nv_bfloat162(__float2bfloat16(v.x - __bfloat162float(h0)),
                           __float2bfloat16(v.y - __bfloat162float(h1)));
    pl[1] = __nv_bfloat162(__float2bfloat16(v.z - __bfloat162float(h2)),
                           __float2bfloat16(v.w - __bfloat162float(h3)));
}

// ---------------- w2 transpose + split: w2t[e][d][f] ----------------
__global__ void split_w2t_kernel(const float* __restrict__ w2) {
    __shared__ float t[32][33];
    const int e = blockIdx.z;
    const int f0 = blockIdx.x * 32, d0 = blockIdx.y * 32;
    const int tx = threadIdx.x, ty = threadIdx.y;   // 32 x 8
#pragma unroll
    for (int j = 0; j < 4; ++j)
        t[ty + j * 8][tx] = w2[((size_t)e * FFN + f0 + ty + j * 8) * DMODEL + d0 + tx];
    __syncthreads();
#pragma unroll
    for (int j = 0; j < 4; ++j) {
        const int dl = ty + j * 8;
        float v = t[tx][dl];
        __nv_bfloat16 hi = __float2bfloat16(v);
        size_t o = ((size_t)e * DMODEL + d0 + dl) * FFN + f0 + tx;
        g_w2t_hi[o] = hi;
        g_w2t_lo[o] = __float2bfloat16(v - __bfloat162float(hi));
    }
}

// ---------------- SwiGLU + split h ----------------
__global__ void h_split_kernel(int n4) {
    int i = blockIdx.x * blockDim.x + threadIdx.x;
    if (i >= n4) return;
    float4 g = reinterpret_cast<const float4*>(g_g)[i];
    float4 l = reinterpret_cast<const float4*>(g_l)[i];
    float4 h;
    h.x = g.x / (1.f + __expf(-g.x)) * l.x;
    h.y = g.y / (1.f + __expf(-g.y)) * l.y;
    h.z = g.z / (1.f + __expf(-g.z)) * l.z;
    h.w = g.w / (1.f + __expf(-g.w)) * l.w;
    __nv_bfloat16 h0 = __float2bfloat16(h.x), h1 = __float2bfloat16(h.y);
    __nv_bfloat16 h2 = __float2bfloat16(h.z), h3 = __float2bfloat16(h.w);
    __nv_bfloat162* ph = reinterpret_cast<__nv_bfloat162*>(g_h_hi) + i * 2;
    ph[0] = __nv_bfloat162(h0, h1);
    ph[1] = __nv_bfloat162(h2, h3);
    __nv_bfloat162* pl = reinterpret_cast<__nv_bfloat162*>(g_h_lo) + i * 2;
    pl[0] = __nv_bfloat162(__float2bfloat16(h.x - __bfloat162float(h0)),
                           __float2bfloat16(h.y - __bfloat162float(h1)));
    pl[1] = __nv_bfloat162(__float2bfloat16(h.z - __bfloat162float(h2)),
                           __float2bfloat16(h.w - __bfloat162float(h3)));
}

// ---------------- GEMM tile constants ----------------
#define STG_SZ 32768
#define OFF_AH 0
#define OFF_AL 8192
#define OFF_BH 16384
#define OFF_BL 24576

// ---------------- GEMM1: g/l = x @ {w1,v1}^T (per-expert gathered rows) ----------
__global__ void __launch_bounds__(256, 1) gemm1_kernel() {
    extern __shared__ char smem[];
    __shared__ int toks[128];
    const unsigned sb = smem_u32(smem);
    const int tid = threadIdx.x, lane = tid & 31, wid = tid >> 5;
    const int bx = blockIdx.x;
    const int sel = bx >> 4;
    const int n0 = (bx & 15) * 128;
    const int e = blockIdx.y;
    const int off = g_off[e], cnt = g_cnt[e];
    const __nv_bfloat16* __restrict__ Bh = sel ? g_v1_hi : g_w1_hi;
    const __nv_bfloat16* __restrict__ Bl = sel ? g_v1_lo : g_w1_lo;
    float* __restrict__ outp = sel ? g_l : g_g;

    const int wm = wid & 1, wn = wid >> 1;
    // swizzle-folded ldmatrix offsets per k-half (ks in {0,1} -> byte col +32)
    unsigned aoffs[2][4], boffs[2][2];
#pragma unroll
    for (int ks = 0; ks < 2; ++ks) {
#pragma unroll
        for (int m = 0; m < 4; ++m) {
            int r = wm * 64 + m * 16 + ((lane >> 3) & 1) * 8 + (lane & 7);
            aoffs[ks][m] = swz(r, ((lane >> 4) << 4) + ks * 32);
        }
#pragma unroll
        for (int np = 0; np < 2; ++np) {
            int r = wn * 32 + np * 16 + ((lane >> 4) << 3) + (lane & 7);
            boffs[ks][np] = swz(r, (((lane >> 3) & 1) << 4) + ks * 32);
        }
    }
    const int prow0 = tid >> 2;
    const int pc16 = (tid & 3) * 16;  // byte col
    const int pc8  = (tid & 3) * 8;   // element col
    unsigned soffs[2];
    soffs[0] = swz(prow0, pc16);
    soffs[1] = swz(prow0 + 64, pc16);

    for (int mt = blockIdx.z; mt * 128 < cnt; mt += gridDim.z) {
        if (tid < 128) {
            int r = mt * 128 + tid;
            toks[tid] = (r < cnt) ? g_pair_tok[off + r] : -1;
        }
        __syncthreads();
        float acc[4][4][4];
#pragma unroll
        for (int m = 0; m < 4; ++m)
#pragma unroll
            for (int n = 0; n < 4; ++n)
#pragma unroll
                for (int q = 0; q < 4; ++q) acc[m][n][q] = 0.f;

        uint4 rAh[2], rAl[2], rBh[2], rBl[2];
        const uint4 z4 = make_uint4(0, 0, 0, 0);
#define G1_LDG(K0)                                                                  \
        {                                                                           \
            _Pragma("unroll")                                                       \
            for (int j = 0; j < 2; ++j) {                                           \
                const int row = prow0 + j * 64;                                     \
                const int tok = toks[row];                                          \
                if (tok >= 0) {                                                     \
                    size_t ao = (size_t)tok * DMODEL + (K0) + pc8;                  \
                    rAh[j] = *reinterpret_cast<const uint4*>(g_xs_hi + ao);         \
                    rAl[j] = *reinterpret_cast<const uint4*>(g_xs_lo + ao);         \
                } else { rAh[j] = z4; rAl[j] = z4; }                                \
                size_t bo = ((size_t)e * FFN + n0 + row) * DMODEL + (K0) + pc8;     \
                rBh[j] = *reinterpret_cast<const uint4*>(Bh + bo);                  \
                rBl[j] = *reinterpret_cast<const uint4*>(Bl + bo);                  \
            }                                                                       \
        }
        G1_LDG(0)
        for (int c = 0; c < DMODEL / 32; ++c) {
            const unsigned so = (unsigned)(c & 1) * STG_SZ;
#pragma unroll
            for (int j = 0; j < 2; ++j) {
                *reinterpret_cast<uint4*>(smem + so + OFF_AH + soffs[j]) = rAh[j];
                *reinterpret_cast<uint4*>(smem + so + OFF_AL + soffs[j]) = rAl[j];
                *reinterpret_cast<uint4*>(smem + so + OFF_BH + soffs[j]) = rBh[j];
                *reinterpret_cast<uint4*>(smem + so + OFF_BL + soffs[j]) = rBl[j];
            }
            if (c + 1 < DMODEL / 32) G1_LDG((c + 1) * 32)
            __syncthreads();
#pragma unroll
            for (int ks = 0; ks < 2; ++ks) {
                unsigned aH[4][4], aL[4][4], bH[2][4], bL[2][4];
#pragma unroll
                for (int m = 0; m < 4; ++m) {
                    ldm4(aH[m], sb + so + OFF_AH + aoffs[ks][m]);
                    ldm4(aL[m], sb + so + OFF_AL + aoffs[ks][m]);
                }
#pragma unroll
                for (int np = 0; np < 2; ++np) {
                    ldm4(bH[np], sb + so + OFF_BH + boffs[ks][np]);
                    ldm4(bL[np], sb + so + OFF_BL + boffs[ks][np]);
                }
#pragma unroll
                for (int np = 0; np < 2; ++np)
#pragma unroll
                    for (int hf = 0; hf < 2; ++hf)
#pragma unroll
                        for (int m = 0; m < 4; ++m)
                            mma16816(acc[m][np * 2 + hf], aH[m], &bH[np][hf * 2]);
#pragma unroll
                for (int np = 0; np < 2; ++np)
#pragma unroll
                    for (int hf = 0; hf < 2; ++hf)
#pragma unroll
                        for (int m = 0; m < 4; ++m)
                            mma16816(acc[m][np * 2 + hf], aH[m], &bL[np][hf * 2]);
#pragma unroll
                for (int np = 0; np < 2; ++np)
#pragma unroll
                    for (int hf = 0; hf < 2; ++hf)
#pragma unroll
                        for (int m = 0; m < 4; ++m)
                            mma16816(acc[m][np * 2 + hf], aL[m], &bH[np][hf * 2]);
            }
        }
        // epilogue: write g or l (fp32)
#pragma unroll
        for (int m = 0; m < 4; ++m)
#pragma unroll
            for (int hf = 0; hf < 2; ++hf) {
                const int rl = mt * 128 + wm * 64 + m * 16 + (lane >> 2) + hf * 8;
                if (rl < cnt) {
                    float* dst = outp + (size_t)(off + rl) * FFN + n0 + wn * 32 + (lane & 3) * 2;
#pragma unroll
                    for (int n = 0; n < 4; ++n) {
                        float2 v = make_float2(acc[m][n][hf * 2], acc[m][n][hf * 2 + 1]);
                        *reinterpret_cast<float2*>(dst + n * 8) = v;
                    }
                }
            }
        __syncthreads();
    }
}

// ---------------- GEMM2: out += gate * (h @ w2t^T) ----------------
__global__ void __launch_bounds__(256, 1) gemm2_kernel(float* __restrict__ out) {
    extern __shared__ char smem[];
    const unsigned sb = smem_u32(smem);
    const int tid = threadIdx.x, lane = tid & 31, wid = tid >> 5;
    const int n0 = blockIdx.x * 128;
    const int e = blockIdx.y;
    const int off = g_off[e], cnt = g_cnt[e];

    const int wm = wid & 1, wn = wid >> 1;
    unsigned aoffs[2][4], boffs[2][2];
#pragma unroll
    for (int ks = 0; ks < 2; ++ks) {
#pragma unroll
        for (int m = 0; m < 4; ++m) {
            int r = wm * 64 + m * 16 + ((lane >> 3) & 1) * 8 + (lane & 7);
            aoffs[ks][m] = swz(r, ((lane >> 4) << 4) + ks * 32);
        }
#pragma unroll
        for (int np = 0; np < 2; ++np) {
            int r = wn * 32 + np * 16 + ((lane >> 4) << 3) + (lane & 7);
            boffs[ks][np] = swz(r, (((lane >> 3) & 1) << 4) + ks * 32);
        }
    }
    const int prow0 = tid >> 2;
    const int pc16 = (tid & 3) * 16;
    const int pc8  = (tid & 3) * 8;
    unsigned soffs[2];
    soffs[0] = swz(prow0, pc16);
    soffs[1] = swz(prow0 + 64, pc16);

    for (int mt = blockIdx.z; mt * 128 < cnt; mt += gridDim.z) {
        float acc[4][4][4];
#pragma unroll
        for (int m = 0; m < 4; ++m)
#pragma unroll
            for (int n = 0; n < 4; ++n)
#pragma unroll
                for (int q = 0; q < 4; ++q) acc[m][n][q] = 0.f;

        uint4 rAh[2], rAl[2], rBh[2], rBl[2];
        const uint4 z4 = make_uint4(0, 0, 0, 0);
#define G2_LDG(K0)                                                                  \
        {                                                                           \
            _Pragma("unroll")                                                       \
            for (int j = 0; j < 2; ++j) {                                           \
                const int row = prow0 + j * 64;                                     \
                const int rl = mt * 128 + row;                                      \
                if (rl < cnt) {                                                     \
                    size_t ao = (size_t)(off + rl) * FFN + (K0) + pc8;              \
                    rAh[j] = *reinterpret_cast<const uint4*>(g_h_hi + ao);          \
                    rAl[j] = *reinterpret_cast<const uint4*>(g_h_lo + ao);          \
                } else { rAh[j] = z4; rAl[j] = z4; }                                \
                size_t bo = ((size_t)e * DMODEL + n0 + row) * FFN + (K0) + pc8;     \
                rBh[j] = *reinterpret_cast<const uint4*>(g_w2t_hi + bo);            \
                rBl[j] = *reinterpret_cast<const uint4*>(g_w2t_lo + bo);            \
            }                                                                       \
        }
        G2_LDG(0)
        for (int c = 0; c < FFN / 32; ++c) {
            const unsigned so = (unsigned)(c & 1) * STG_SZ;
#pragma unroll
            for (int j = 0; j < 2; ++j) {
                *reinterpret_cast<uint4*>(smem + so + OFF_AH + soffs[j]) = rAh[j];
                *reinterpret_cast<uint4*>(smem + so + OFF_AL + soffs[j]) = rAl[j];
                *reinterpret_cast<uint4*>(smem + so + OFF_BH + soffs[j]) = rBh[j];
                *reinterpret_cast<uint4*>(smem + so + OFF_BL + soffs[j]) = rBl[j];
            }
            if (c + 1 < FFN / 32) G2_LDG((c + 1) * 32)
            __syncthreads();
#pragma unroll
            for (int ks = 0; ks < 2; ++ks) {
                unsigned aH[4][4], aL[4][4], bH[2][4], bL[2][4];
#pragma unroll
                for (int m = 0; m < 4; ++m) {
                    ldm4(aH[m], sb + so + OFF_AH + aoffs[ks][m]);
                    ldm4(aL[m], sb + so + OFF_AL + aoffs[ks][m]);
                }
#pragma unroll
                for (int np = 0; np < 2; ++np) {
                    ldm4(bH[np], sb + so + OFF_BH + boffs[ks][np]);
                    ldm4(bL[np], sb + so + OFF_BL + boffs[ks][np]);
                }
#pragma unroll
                for (int np = 0; np < 2; ++np)
#pragma unroll
                    for (int hf = 0; hf < 2; ++hf)
#pragma unroll
                        for (int m = 0; m < 4; ++m)
                            mma16816(acc[m][np * 2 + hf], aH[m], &bH[np][hf * 2]);
#pragma unroll
                for (int np = 0; np < 2; ++np)
#pragma unroll
                    for (int hf = 0; hf < 2; ++hf)
#pragma unroll
                        for (int m = 0; m < 4; ++m)
                            mma16816(acc[m][np * 2 + hf], aH[m], &bL[np][hf * 2]);
#pragma unroll
                for (int np = 0; np < 2; ++np)
#pragma unroll
                    for (int hf = 0; hf < 2; ++hf)
#pragma unroll
                        for (int m = 0; m < 4; ++m)
                            mma16816(acc[m][np * 2 + hf], aL[m], &bH[np][hf * 2]);
            }
        }
        // epilogue: gate-scaled atomic combine (2 adds per output elem total)
#pragma unroll
        for (int m = 0; m < 4; ++m)
#pragma unroll
            for (int hf = 0; hf < 2; ++hf) {
                const int rl = mt * 128 + wm * 64 + m * 16 + (lane >> 2) + hf * 8;
                if (rl < cnt) {
                    const int   tok = g_pair_tok[off + rl];
                    const float gt  = g_pair_gate[off + rl];
                    float* dst = out + (size_t)tok * DMODEL + n0 + wn * 32 + (lane & 3) * 2;
#pragma unroll
                    for (int n = 0; n < 4; ++n) {
                        atomicAdd(dst + n * 8 + 0, gt * acc[m][n][hf * 2]);
                        atomicAdd(dst + n * 8 + 1, gt * acc[m][n][hf * 2 + 1]);
                    }
                }
            }
        __syncthreads();
    }
}

// ---------------- launch ----------------
extern "C" void kernel_launch(void* const* d_in, const int* in_sizes, int n_in,
                              void* d_out, int out_size) {
    const float* x  = (const float*)d_in[0];
    const float* w1 = (const float*)d_in[1];
    const float* v1 = (const float*)d_in[2];
    const float* w2 = (const float*)d_in[3];
    const float* rw = (const float*)d_in[4];
    float* out = (float*)d_out;

    cudaFuncSetAttribute(gemm1_kernel, cudaFuncAttributeMaxDynamicSharedMemorySize, 2 * STG_SZ);
    cudaFuncSetAttribute(gemm2_kernel, cudaFuncAttributeMaxDynamicSharedMemorySize, 2 * STG_SZ);

    init_kernel<<<(T_TOK * DMODEL + 255) / 256, 256>>>(out, T_TOK * DMODEL);
    router_kernel<<<T_TOK, 256>>>(x, rw);
    offsets_kernel<<<1, 1>>>();
    scatter_kernel<<<(T_TOK + 255) / 256, 256>>>();

    __nv_bfloat16 *xs_hi, *xs_lo, *w1_hi, *w1_lo, *v1_hi, *v1_lo;
    cudaGetSymbolAddress((void**)&xs_hi, g_xs_hi);
    cudaGetSymbolAddress((void**)&xs_lo, g_xs_lo);
    cudaGetSymbolAddress((void**)&w1_hi, g_w1_hi);
    cudaGetSymbolAddress((void**)&w1_lo, g_w1_lo);
    cudaGetSymbolAddress((void**)&v1_hi, g_v1_hi);
    cudaGetSymbolAddress((void**)&v1_lo, g_v1_lo);

    const int nx4 = T_TOK * DMODEL / 4;
    const int nw4 = NEXP * FFN * DMODEL / 4;
    split_kernel<<<(nx4 + 255) / 256, 256>>>(x, xs_hi, xs_lo, nx4);
    split_kernel<<<(nw4 + 255) / 256, 256>>>(w1, w1_hi, w1_lo, nw4);
    split_kernel<<<(nw4 + 255) / 256, 256>>>(v1, v1_hi, v1_lo, nw4);
    split_w2t_kernel<<<dim3(FFN / 32, DMODEL / 32, NEXP), dim3(32, 8)>>>(w2);

    gemm1_kernel<<<dim3(32, NEXP, 4), 256, 2 * STG_SZ>>>();
    const int nh4 = NPAIR * FFN / 4;
    h_split_kernel<<<(nh4 + 255) / 256, 256>>>(nh4);
    gemm2_kernel<<<dim3(DMODEL / 128, NEXP, 8), 256, 2 * STG_SZ>>>(out);
}